// round 16
// baseline (speedup 1.0000x reference)
#include <cuda_runtime.h>
#include <math.h>

// DBI_44985487458968 — Davies-Bouldin index. N=2M x 64 f32, K=100.
// v5 = v3 accum core (red.v4 into 148 L2-resident scratch copies) with the
// sq-reduction trimmed (2-step shuffle + single scalar red for Sxx+count:
// 8 -> 6 MIO warp-ops per 2 points), + conflict-free finalize (transposed
// padded tile At[64][104]; v3's finalize measured 121us of 32-way LDS
// conflicts at row stride 64).

#define KC     100
#define DF     64
#define KCP    104                  // padded K stride: kills bank conflicts
#define NCOPY  148
#define C_F4   1700                 // per-copy float4s: 1600 sums + 100 aux
#define COPY_F (C_F4 * 4)           // 6800 floats per copy
#define NACC   COPY_F               // reduced: 6400 sums + 100*(sq,cnt,_,_)

__device__ float4 g_scratch[NCOPY * C_F4];   // 4.03 MB, L2-resident
__device__ float  g_acc[NACC];
__device__ int    g_id64;                    // clustering int64 vs int32

__device__ __forceinline__ void red_add_v4(float4* addr, float x, float y, float z, float w) {
    asm volatile("red.global.add.v4.f32 [%0], {%1,%2,%3,%4};"
                 :: "l"(addr), "f"(x), "f"(y), "f"(z), "f"(w) : "memory");
}
__device__ __forceinline__ void red_add_f32(float* addr, float v) {
    asm volatile("red.global.add.f32 [%0], %1;"
                 :: "l"(addr), "f"(v) : "memory");
}

// ------------------------------------------------------- init + probe ----
__global__ void dbi_init_kernel(const unsigned int* __restrict__ cl_u32, int nprobe) {
    int i = blockIdx.x * blockDim.x + threadIdx.x;
    int total = NCOPY * C_F4;
    if (i < total) g_scratch[i] = make_float4(0.f, 0.f, 0.f, 0.f);
    if (i == 0) {
        // int64 ids < 100 => every odd u32 word is zero; int32 ids make them ids.
        int any_nonzero = 0;
        for (int k = 0; k < nprobe; k++)
            any_nonzero |= (cl_u32[2 * k + 1] != 0u);
        g_id64 = !any_nonzero;
    }
}

// ---------------------------------------------------------- accumulate ----
// Half-warp per point: lanes 0-15 point j, lanes 16-31 point j+1.
// Lane l15 owns dims [4*l15,4*l15+4) as one float4 -> one red.v4.
// sq: in-lane dot4, then 2 xor-shuffles (o=8,4, width 16) leave the 4 group
// sums in lanes l15=0..3; those lanes red.f32 into aux[c].x and lane l15==4
// reds 1.0f into aux[c].y (count) -- one predicated instruction.
__global__ __launch_bounds__(256) void dbi_accum_kernel(
    const float* __restrict__ pts,
    const void*  __restrict__ cl_raw,
    int n)
{
    const int id64 = g_id64;
    const unsigned int* clu = (const unsigned int*)cl_raw;
    const float4* f4 = (const float4*)pts;

    const int lane   = threadIdx.x & 31;
    const int half   = lane >> 4;
    const int l15    = lane & 15;
    const int wGlob  = (blockIdx.x * blockDim.x + threadIdx.x) >> 5;
    const int nWarps = (gridDim.x * blockDim.x) >> 5;

    float4* base = g_scratch + (blockIdx.x % NCOPY) * C_F4;
    float4* aux  = base + 1600;

    const int nChunks = n >> 5;            // 32 points per chunk
    for (int ch = wGlob; ch < nChunks; ch += nWarps) {
        const int pbase = ch << 5;
        const int c_reg = (int)clu[id64 ? (unsigned)(2 * (pbase + lane))
                                        : (unsigned)(pbase + lane)];
        const size_t fbase = (size_t)pbase << 4;     // 16 float4 per point

        #pragma unroll 4
        for (int j = 0; j < 32; j += 2) {
            float4 v = __ldcs(&f4[fbase + (size_t)(j << 4) + lane]);
            int c = __shfl_sync(0xffffffffu, c_reg, j + half);
            float sq = v.x * v.x + v.y * v.y + v.z * v.z + v.w * v.w;
            sq += __shfl_xor_sync(0xffffffffu, sq, 8, 16);
            sq += __shfl_xor_sync(0xffffffffu, sq, 4, 16);
            // lanes l15 in {0,1,2,3} now hold the 4 group sums (total = ||x||^2)
            if ((unsigned)c < KC) {
                red_add_v4(base + c * 16 + l15, v.x, v.y, v.z, v.w);
                if (l15 < 5) {
                    float  val  = (l15 < 4) ? sq : 1.0f;
                    float* addr = (l15 < 4) ? &aux[c].x : &aux[c].y;
                    red_add_f32(addr, val);
                }
            }
        }
    }

    // tail: one warp per remaining point, lanes 0-15 active (full butterfly)
    const int tail0 = nChunks << 5;
    const int ntail = n - tail0;
    if (wGlob < ntail) {
        const int p = tail0 + wGlob;
        const int c = (int)clu[id64 ? (unsigned)(2 * p) : (unsigned)p];
        float4 v = make_float4(0.f, 0.f, 0.f, 0.f);
        if (lane < 16) v = f4[((size_t)p << 4) + l15];
        float sq = v.x * v.x + v.y * v.y + v.z * v.z + v.w * v.w;
        #pragma unroll
        for (int o = 8; o; o >>= 1)
            sq += __shfl_xor_sync(0xffffffffu, sq, o, 16);
        if ((unsigned)c < KC && lane < 16) {
            red_add_v4(base + c * 16 + l15, v.x, v.y, v.z, v.w);
            if (lane == 0) {
                red_add_f32(&aux[c].x, sq);
                red_add_f32(&aux[c].y, 1.0f);
            }
        }
    }
}

// --------------------------------------------------------- copy-reduce ----
__global__ __launch_bounds__(256) void dbi_reduce_kernel() {
    int i = blockIdx.x * blockDim.x + threadIdx.x;
    if (i >= NACC) return;
    const float* sf = (const float*)g_scratch;
    float acc = 0.0f;
    #pragma unroll 4
    for (int cpy = 0; cpy < NCOPY; cpy++)
        acc += sf[cpy * COPY_F + i];
    g_acc[i] = acc;
}

// ------------------------------------------------------------ finalize ----
// Transposed padded centroid tile: At[d][c], stride KCP=104 (104 mod 32 = 8):
// per-lane consecutive c => consecutive banks (conflict-free); uniform j
// => broadcast. Own row register-cached for the Rij sweep.
__global__ __launch_bounds__(128) void dbi_final_kernel(float* __restrict__ out) {
    __shared__ float At[DF][KCP];       // 26.6 KB
    __shared__ float Si[KC];
    __shared__ float rowmax[KC];
    const int tid = threadIdx.x;

    // centroids: At[d][c] = (0.001 + Sx[c][d]) / (1 + n_c)
    for (int i = tid; i < KC * DF; i += blockDim.x) {
        int c = i >> 6, d = i & 63;
        float cnt = 1.0f + g_acc[6400 + c * 4 + 1];
        At[d][c] = (0.001f + g_acc[c * DF + d]) / cnt;
    }
    __syncthreads();

    // Si via  Sum||x-A||^2 = Sxx - 2 A.Sx + n ||A||^2
    // with    A.Sx = cnt*||A||^2 - 0.001*sum(A)   (since Sx = A*cnt - 0.001)
    if (tid < KC) {
        const int c = tid;
        float nk  = g_acc[6400 + c * 4 + 1];
        float cnt = 1.0f + nk;
        float sxx = g_acc[6400 + c * 4 + 0];
        float a2 = 0.0f, suma = 0.0f;
        #pragma unroll 16
        for (int d = 0; d < DF; d++) {
            float a = At[d][c];                 // conflict-free (consec. banks)
            a2   = fmaf(a, a, a2);
            suma += a;
        }
        float dot = cnt * a2 - 0.001f * suma;
        float sq  = sxx - 2.0f * dot + nk * a2;
        Si[c] = sqrtf((0.001f + sq) / cnt);
    }
    __syncthreads();

    // Rij row maxes: own row in registers, other row via LDS broadcast
    if (tid < KC) {
        const int i = tid;
        float myA[DF];
        #pragma unroll
        for (int d = 0; d < DF; d++) myA[d] = At[d][i];
        const float si = Si[i];
        float m = 0.0f;
        for (int j = 0; j < KC; j++) {
            if (j == i) continue;
            float ss = 0.0f;
            #pragma unroll 16
            for (int d = 0; d < DF; d++) {
                float df = myA[d] - At[d][j];   // broadcast LDS
                ss = fmaf(df, df, ss);
            }
            m = fmaxf(m, (si + Si[j]) * rsqrtf(ss));
        }
        rowmax[i] = m;
    }
    __syncthreads();

    if (tid == 0) {
        float sum = 0.0f;
        for (int c = 0; c < KC; c++) sum += rowmax[c];
        out[0] = sum / (float)KC;
    }
}

// -------------------------------------------------------------- launch ----
extern "C" void kernel_launch(void* const* d_in, const int* in_sizes, int n_in,
                              void* d_out, int out_size) {
    // binding by element-count ratio (points = 64x ids)
    const long long s0 = in_sizes[0];
    const long long s1 = (n_in > 1) ? in_sizes[1] : 0;

    const float* pts;
    const void*  cl;
    int n;
    if (s0 == 64 * s1) {
        pts = (const float*)d_in[0];
        cl  = d_in[1];
        n   = (int)s1;
    } else {
        pts = (const float*)d_in[1];
        cl  = d_in[0];
        n   = (int)s0;
    }

    int nprobe = n / 2 < 128 ? n / 2 : 128;   // probe bounds safe for either dtype
    int initThreads = NCOPY * C_F4;           // one thread per float4 to zero
    dbi_init_kernel<<<(initThreads + 255) / 256, 256>>>((const unsigned int*)cl, nprobe);
    dbi_accum_kernel<<<1184, 256>>>(pts, cl, n);
    dbi_reduce_kernel<<<(NACC + 255) / 256, 256>>>();
    dbi_final_kernel<<<1, 128>>>((float*)d_out);
}

// round 17
// speedup vs baseline: 1.7639x; 1.7639x over previous
#include <cuda_runtime.h>
#include <math.h>

// DBI_44985487458968 — Davies-Bouldin index. N=2M x 64 f32, K=100.
// v6 = v3 accum verbatim (red.v4 into 148 L2-resident scratch copies,
// measured 143us; v5's scalar-red variant regressed to ~199us -> reverted)
// + parallel finalize: the old 1-block final kernel was parallelism-starved
// (grid=1, 4 warps, ~30cyc exposed latency per inner iter = 113us measured).
// New: 40-block pairs kernel, thread per (i,j), atomicMax rowmax, tiny out.

#define KC     100
#define DF     64
#define KCP    104                 // padded stride for the centroid tile
#define NCOPY  148
#define C_F4   1700                // per-copy float4s: 1600 sums + 100 aux
#define COPY_F (C_F4 * 4)          // 6800 floats per copy
#define NACC   COPY_F              // reduced: 6400 sums + 100*(sq,cnt,_,_)

__device__ float4 g_scratch[NCOPY * C_F4];   // 4.03 MB, L2-resident
__device__ float  g_acc[NACC];
__device__ int    g_rowmax[KC];              // rowwise max(Rij) as ordered int bits
__device__ int    g_id64;                    // clustering int64 vs int32

__device__ __forceinline__ void red_add_v4(float4* addr, float x, float y, float z, float w) {
    asm volatile("red.global.add.v4.f32 [%0], {%1,%2,%3,%4};"
                 :: "l"(addr), "f"(x), "f"(y), "f"(z), "f"(w) : "memory");
}

// ------------------------------------------------------- init + probe ----
__global__ void dbi_init_kernel(const unsigned int* __restrict__ cl_u32, int nprobe) {
    int i = blockIdx.x * blockDim.x + threadIdx.x;
    int total = NCOPY * C_F4;
    if (i < total) g_scratch[i] = make_float4(0.f, 0.f, 0.f, 0.f);
    if (i < KC) g_rowmax[i] = 0;             // floats are >0; int 0 is the floor
    if (i == 0) {
        // int64 ids < 100 => every odd u32 word is zero; int32 ids make them ids.
        int any_nonzero = 0;
        for (int k = 0; k < nprobe; k++)
            any_nonzero |= (cl_u32[2 * k + 1] != 0u);
        g_id64 = !any_nonzero;
    }
}

// ---------------------------------------------------------- accumulate ----
// (v3 verbatim, measured ~143us.) Half-warp per point: lanes 0-15 point j,
// lanes 16-31 point j+1. Lane l15 owns dims [4*l15,4*l15+4) -> one red.v4.
// sq: dot4 + 4-step xor-shuffle width 16; lanes 0/16 emit one aux red.v4 =
// (sq, 1.0, 0, 0) covering Sxx and count together.
__global__ __launch_bounds__(256) void dbi_accum_kernel(
    const float* __restrict__ pts,
    const void*  __restrict__ cl_raw,
    int n)
{
    const int id64 = g_id64;
    const unsigned int* clu = (const unsigned int*)cl_raw;
    const float4* f4 = (const float4*)pts;

    const int lane   = threadIdx.x & 31;
    const int half   = lane >> 4;
    const int l15    = lane & 15;
    const int wGlob  = (blockIdx.x * blockDim.x + threadIdx.x) >> 5;
    const int nWarps = (gridDim.x * blockDim.x) >> 5;

    float4* base = g_scratch + (blockIdx.x % NCOPY) * C_F4;
    float4* aux  = base + 1600;

    const int nChunks = n >> 5;            // 32 points per chunk
    for (int ch = wGlob; ch < nChunks; ch += nWarps) {
        const int pbase = ch << 5;
        const int c_reg = (int)clu[id64 ? (unsigned)(2 * (pbase + lane))
                                        : (unsigned)(pbase + lane)];
        const size_t fbase = (size_t)pbase << 4;     // 16 float4 per point

        #pragma unroll 4
        for (int j = 0; j < 32; j += 2) {
            float4 v = __ldcs(&f4[fbase + (size_t)(j << 4) + lane]);
            int c = __shfl_sync(0xffffffffu, c_reg, j + half);
            float sq = v.x * v.x + v.y * v.y + v.z * v.z + v.w * v.w;
            #pragma unroll
            for (int o = 8; o; o >>= 1)
                sq += __shfl_xor_sync(0xffffffffu, sq, o, 16);
            if ((unsigned)c < KC) {
                red_add_v4(base + c * 16 + l15, v.x, v.y, v.z, v.w);
                if (l15 == 0)
                    red_add_v4(aux + c, sq, 1.0f, 0.0f, 0.0f);
            }
        }
    }

    // tail: one warp per remaining point, lanes 0-15 active
    const int tail0 = nChunks << 5;
    const int ntail = n - tail0;
    if (wGlob < ntail) {
        const int p = tail0 + wGlob;
        const int c = (int)clu[id64 ? (unsigned)(2 * p) : (unsigned)p];
        float4 v = make_float4(0.f, 0.f, 0.f, 0.f);
        if (lane < 16) v = f4[((size_t)p << 4) + l15];
        float sq = v.x * v.x + v.y * v.y + v.z * v.z + v.w * v.w;
        #pragma unroll
        for (int o = 8; o; o >>= 1)
            sq += __shfl_xor_sync(0xffffffffu, sq, o, 16);
        if ((unsigned)c < KC && lane < 16) {
            red_add_v4(base + c * 16 + l15, v.x, v.y, v.z, v.w);
            if (lane == 0)
                red_add_v4(aux + c, sq, 1.0f, 0.0f, 0.0f);
        }
    }
}

// --------------------------------------------------------- copy-reduce ----
__global__ __launch_bounds__(256) void dbi_reduce_kernel() {
    int i = blockIdx.x * blockDim.x + threadIdx.x;
    if (i >= NACC) return;
    const float* sf = (const float*)g_scratch;
    float acc = 0.0f;
    #pragma unroll 4
    for (int cpy = 0; cpy < NCOPY; cpy++)
        acc += sf[cpy * COPY_F + i];
    g_acc[i] = acc;
}

// ---------------------------------------------------------------- pairs ----
// Thread per (i,j) pair, 40 blocks x 256 threads cover 100x100. Each block
// rebuilds the centroid tile At[d][c] (padded stride) + Si[c] from g_acc
// (L2-resident; cheap), then each thread computes Rij and atomicMax-folds
// into g_rowmax[i] (positive floats compare correctly as ints).
__global__ __launch_bounds__(256) void dbi_pairs_kernel() {
    __shared__ float At[DF][KCP];       // 26.6 KB
    __shared__ float Si[KC];
    const int tid = threadIdx.x;

    for (int i = tid; i < KC * DF; i += 256) {
        int c = i >> 6, d = i & 63;
        float cnt = 1.0f + g_acc[6400 + c * 4 + 1];
        At[d][c] = (0.001f + g_acc[c * DF + d]) / cnt;
    }
    __syncthreads();

    if (tid < KC) {
        const int c = tid;
        float nk  = g_acc[6400 + c * 4 + 1];
        float cnt = 1.0f + nk;
        float sxx = g_acc[6400 + c * 4 + 0];
        float a2 = 0.0f, suma = 0.0f;
        #pragma unroll 16
        for (int d = 0; d < DF; d++) {
            float a = At[d][c];             // lanes read consecutive c: no conflict
            a2   = fmaf(a, a, a2);
            suma += a;
        }
        // A.Sx = cnt*||A||^2 - 0.001*sum(A)  (exact: Sx = A*cnt - 0.001)
        float dot = cnt * a2 - 0.001f * suma;
        float sq  = sxx - 2.0f * dot + nk * a2;
        Si[c] = sqrtf((0.001f + sq) / cnt);
    }
    __syncthreads();

    const int pair = blockIdx.x * 256 + tid;
    if (pair < KC * KC) {
        const int i = pair / KC;
        const int j = pair - i * KC;
        if (i != j) {
            float ss = 0.0f;
            #pragma unroll 16
            for (int d = 0; d < DF; d++) {
                float df = At[d][i] - At[d][j];   // j consecutive per lane: no conflict
                ss = fmaf(df, df, ss);
            }
            float r = (Si[i] + Si[j]) * rsqrtf(ss);
            atomicMax(&g_rowmax[i], __float_as_int(r));
        }
    }
}

// ------------------------------------------------------------------ out ----
__global__ void dbi_out_kernel(float* __restrict__ out) {
    const int lane = threadIdx.x;
    float v = 0.0f;
    for (int c = lane; c < KC; c += 32)
        v += __int_as_float(g_rowmax[c]);
    #pragma unroll
    for (int o = 16; o; o >>= 1)
        v += __shfl_xor_sync(0xffffffffu, v, o);
    if (lane == 0) out[0] = v / (float)KC;
}

// -------------------------------------------------------------- launch ----
extern "C" void kernel_launch(void* const* d_in, const int* in_sizes, int n_in,
                              void* d_out, int out_size) {
    // binding by element-count ratio (points = 64x ids)
    const long long s0 = in_sizes[0];
    const long long s1 = (n_in > 1) ? in_sizes[1] : 0;

    const float* pts;
    const void*  cl;
    int n;
    if (s0 == 64 * s1) {
        pts = (const float*)d_in[0];
        cl  = d_in[1];
        n   = (int)s1;
    } else {
        pts = (const float*)d_in[1];
        cl  = d_in[0];
        n   = (int)s0;
    }

    int nprobe = n / 2 < 128 ? n / 2 : 128;   // probe bounds safe for either dtype
    int initThreads = NCOPY * C_F4;           // one thread per float4 to zero
    dbi_init_kernel<<<(initThreads + 255) / 256, 256>>>((const unsigned int*)cl, nprobe);
    dbi_accum_kernel<<<1184, 256>>>(pts, cl, n);
    dbi_reduce_kernel<<<(NACC + 255) / 256, 256>>>();
    dbi_pairs_kernel<<<(KC * KC + 255) / 256, 256>>>();
    dbi_out_kernel<<<1, 32>>>((float*)d_out);
}